// round 11
// baseline (speedup 1.0000x reference)
#include <cuda_runtime.h>
#include <cstdint>

// Problem constants
#define LDIM   128
#define RDIM   2048
#define EDIM   32
#define FDIM   64
#define KTOT   2048
#define BATCH  8

// Tiling: CTA = 128L x 256R x (ECH*64)k, 256 threads, thread tile 16L x 8R
#define KT       16
#define RT       256
#define ECH      2
#define NSTAGE   ((ECH*FDIM)/KT)     // 8
#define NTHREADS 256
#define AROW     132                 // A tile padded row (words)
#define BROW     260                 // B tile padded row (words)
#define ZROW     260                 // zb padded row (words)

// rbf(d,e) = exp(-((d-mu_e)/sigma)^2) = 2^(-(KC*(d-mu_e))^2)
#define KC_CONST   3.2029930899845557f
#define MU_STEP    (12.0f/31.0f)

// dynamic smem layout (floats)
#define SM_A      0
#define SM_B      (2*KT*AROW)                  // 4224
#define SM_ZB     (SM_B + 2*KT*BROW)           // 12544
#define SM_FLOATS (SM_ZB + LDIM*ZROW)          // 45824
#define SMEM_BYTES (SM_FLOATS*4)               // 183296 B

__device__ __forceinline__ unsigned long long dup2(float x) {
    unsigned long long r;
    unsigned int u = __float_as_uint(x);
    asm("mov.b64 %0, {%1, %1};" : "=l"(r) : "r"(u));
    return r;
}
__device__ __forceinline__ void fma2(unsigned long long &acc,
                                     unsigned long long a,
                                     unsigned long long b) {
    asm("fma.rn.f32x2 %0, %1, %2, %0;" : "+l"(acc) : "l"(a), "l"(b));
}
__device__ __forceinline__ void unpack2(unsigned long long v, float &lo, float &hi) {
    unsigned int a, b;
    asm("mov.b64 {%0, %1}, %2;" : "=r"(a), "=r"(b) : "l"(v));
    lo = __uint_as_float(a);
    hi = __uint_as_float(b);
}
__device__ __forceinline__ float ex2a(float x) {
    float r; asm("ex2.approx.ftz.f32 %0, %1;" : "=f"(r) : "f"(x)); return r;
}
__device__ __forceinline__ float sqrta(float x) {
    float r; asm("sqrt.approx.f32 %0, %1;" : "=f"(r) : "f"(x)); return r;
}

__global__ void ff_init_kernel(float* out) {
    if (threadIdx.x < BATCH) out[threadIdx.x] = 0.0f;
}

__global__ void __launch_bounds__(NTHREADS, 1)
ff_main_kernel(const float* __restrict__ ligf,
               const float* __restrict__ recf,
               const float* __restrict__ ligc,
               const float* __restrict__ recc,
               float* __restrict__ out)
{
    extern __shared__ __align__(16) float smem[];
    float* As = smem + SM_A;
    float* Bs = smem + SM_B;
    float* zb = smem + SM_ZB;

    const int tid  = threadIdx.x;
    const int lane = tid & 31;
    const int w    = tid >> 5;          // 0..7; owns l = w*16 .. w*16+15
    const int l0   = w * 16;
    // lane owns r: j<4 -> 4*lane+j ; j>=4 -> 128+4*lane+(j-4)

    const int rt = blockIdx.x;          // 0..7
    const int ec = blockIdx.y;          // 0..15
    const int b  = blockIdx.z;          // 0..7

    const int r0    = rt * RT;
    const int e0    = ec * ECH;
    const int kbase = e0 * FDIM;

    const float* Ag = ligf + (size_t)b * LDIM * KTOT + kbase;
    const float* Bg = recf + ((size_t)b * RDIM + r0) * KTOT + kbase;

    // ---- stage coords into smem (reuse A tile area), then build zb ----
    {
        float* lc = As;                 // [128][3] = 384 floats
        float* rc = As + 512;           // [256][3] = 768 floats
        for (int i = tid; i < LDIM * 3; i += NTHREADS)
            lc[i] = ligc[(size_t)b * LDIM * 3 + i];
        for (int i = tid; i < RT * 3; i += NTHREADS)
            rc[i] = recc[((size_t)b * RDIM + r0) * 3 + i];
        __syncthreads();

        const int l  = tid >> 1;            // 0..127
        const int rb = (tid & 1) * 128;     // 0 / 128
        const float lx = lc[l * 3], ly = lc[l * 3 + 1], lz = lc[l * 3 + 2];
        float* zrow = zb + l * ZROW + rb;
        #pragma unroll 4
        for (int i = 0; i < 128; i++) {
            const float* q = rc + (rb + i) * 3;
            float dx = lx - q[0], dy = ly - q[1], dz = lz - q[2];
            float dd = fmaf(dx, dx, fmaf(dy, dy, dz * dz));
            zrow[i] = KC_CONST * sqrta(dd);
        }
        __syncthreads();
    }

    // acc[p][j]: packed {l = l0+2p, l0+2p+1} x r-slot j
    unsigned long long acc[8][8];
    #pragma unroll
    for (int p = 0; p < 8; p++)
        #pragma unroll
        for (int j = 0; j < 8; j++)
            acc[p][j] = 0ULL;

    float u_acc = 0.0f;

    // staging: A 128x16/stage = 2 float4/thread; B 256x16 = 4 float4/thread
    const int srow = tid >> 2;          // 0..63
    const int scol = (tid & 3) * 4;     // 0,4,8,12

    float4 pa0, pa1, pb0, pb1, pb2, pb3;
    pa0 = *(const float4*)(Ag + (size_t)srow * KTOT + scol);
    pa1 = *(const float4*)(Ag + (size_t)(srow + 64) * KTOT + scol);
    pb0 = *(const float4*)(Bg + (size_t)srow * KTOT + scol);
    pb1 = *(const float4*)(Bg + (size_t)(srow + 64) * KTOT + scol);
    pb2 = *(const float4*)(Bg + (size_t)(srow + 128) * KTOT + scol);
    pb3 = *(const float4*)(Bg + (size_t)(srow + 192) * KTOT + scol);

    #pragma unroll 1
    for (int s = 0; s < NSTAGE; s++) {
        const int buf = s & 1;
        float* Asb = As + buf * (KT * AROW);
        float* Bsb = Bs + buf * (KT * BROW);

        // store staged tile
        {
            float va0[4] = {pa0.x, pa0.y, pa0.z, pa0.w};
            float va1[4] = {pa1.x, pa1.y, pa1.z, pa1.w};
            float vb0[4] = {pb0.x, pb0.y, pb0.z, pb0.w};
            float vb1[4] = {pb1.x, pb1.y, pb1.z, pb1.w};
            float vb2[4] = {pb2.x, pb2.y, pb2.z, pb2.w};
            float vb3[4] = {pb3.x, pb3.y, pb3.z, pb3.w};
            #pragma unroll
            for (int j = 0; j < 4; j++) {
                Asb[(scol + j) * AROW + srow]       = va0[j];
                Asb[(scol + j) * AROW + srow + 64]  = va1[j];
                Bsb[(scol + j) * BROW + srow]       = vb0[j];
                Bsb[(scol + j) * BROW + srow + 64]  = vb1[j];
                Bsb[(scol + j) * BROW + srow + 128] = vb2[j];
                Bsb[(scol + j) * BROW + srow + 192] = vb3[j];
            }
        }
        __syncthreads();

        // prefetch next stage
        if (s + 1 < NSTAGE) {
            const int ko = (s + 1) * KT + scol;
            pa0 = *(const float4*)(Ag + (size_t)srow * KTOT + ko);
            pa1 = *(const float4*)(Ag + (size_t)(srow + 64) * KTOT + ko);
            pb0 = *(const float4*)(Bg + (size_t)srow * KTOT + ko);
            pb1 = *(const float4*)(Bg + (size_t)(srow + 64) * KTOT + ko);
            pb2 = *(const float4*)(Bg + (size_t)(srow + 128) * KTOT + ko);
            pb3 = *(const float4*)(Bg + (size_t)(srow + 192) * KTOT + ko);
        }

        // ---- main compute: KT k-steps, 16L x 8R per thread ----
        #pragma unroll 4
        for (int k = 0; k < KT; k++) {
            // A: 8 l-pairs (64B) via 4 LDS.128, same addr warp-wide
            unsigned long long a2[8];
            {
                const ulonglong2* Ar = (const ulonglong2*)(Asb + k * AROW + l0);
                ulonglong2 t0 = Ar[0];
                ulonglong2 t1 = Ar[1];
                ulonglong2 t2 = Ar[2];
                ulonglong2 t3 = Ar[3];
                a2[0] = t0.x; a2[1] = t0.y; a2[2] = t1.x; a2[3] = t1.y;
                a2[4] = t2.x; a2[5] = t2.y; a2[6] = t3.x; a2[7] = t3.y;
            }
            // B: two strided float4 groups, both conflict-free LDS.128
            float4 bf0 = *(const float4*)(Bsb + k * BROW + 4 * lane);
            float4 bf1 = *(const float4*)(Bsb + k * BROW + 128 + 4 * lane);
            unsigned long long b2[8];
            b2[0] = dup2(bf0.x); b2[1] = dup2(bf0.y);
            b2[2] = dup2(bf0.z); b2[3] = dup2(bf0.w);
            b2[4] = dup2(bf1.x); b2[5] = dup2(bf1.y);
            b2[6] = dup2(bf1.z); b2[7] = dup2(bf1.w);

            #pragma unroll
            for (int p = 0; p < 8; p++)
                #pragma unroll
                for (int j = 0; j < 8; j++)
                    fma2(acc[p][j], a2[p], b2[j]);
        }

        // ---- epilogue fold at each e boundary (every 4 stages) ----
        if ((s & 3) == 3) {
            const int e = e0 + (s >> 2);
            const float c2 = KC_CONST * MU_STEP * (float)e;
            #pragma unroll
            for (int p = 0; p < 8; p++) {
                const float* z0p = zb + (l0 + 2 * p) * ZROW + 4 * lane;
                const float* z1p = z0p + ZROW;
                float4 za0 = *(const float4*)(z0p);
                float4 za1 = *(const float4*)(z0p + 128);
                float4 zc0 = *(const float4*)(z1p);
                float4 zc1 = *(const float4*)(z1p + 128);
                float z0v[8] = {za0.x, za0.y, za0.z, za0.w,
                                za1.x, za1.y, za1.z, za1.w};
                float z1v[8] = {zc0.x, zc0.y, zc0.z, zc0.w,
                                zc1.x, zc1.y, zc1.z, zc1.w};
                #pragma unroll
                for (int j = 0; j < 8; j++) {
                    float dot0, dot1;
                    unpack2(acc[p][j], dot0, dot1);
                    float q0 = z0v[j] - c2;
                    float q1 = z1v[j] - c2;
                    u_acc = fmaf(ex2a(-q0 * q0), dot0, u_acc);
                    u_acc = fmaf(ex2a(-q1 * q1), dot1, u_acc);
                    acc[p][j] = 0ULL;
                }
            }
        }
    }

    // ---- block reduction + atomic accumulate into U[b] ----
    #pragma unroll
    for (int o = 16; o > 0; o >>= 1)
        u_acc += __shfl_xor_sync(0xffffffffu, u_acc, o);

    __syncthreads();
    float* red = smem;
    if (lane == 0) red[w] = u_acc;
    __syncthreads();
    if (tid == 0) {
        float ssum = 0.0f;
        #pragma unroll
        for (int ww = 0; ww < NTHREADS / 32; ww++) ssum += red[ww];
        atomicAdd(out + b, ssum * 0.01f);   // ENERGY_SCALE
    }
}

extern "C" void kernel_launch(void* const* d_in, const int* in_sizes, int n_in,
                              void* d_out, int out_size) {
    (void)in_sizes; (void)n_in; (void)out_size;
    const float* lig_feat  = (const float*)d_in[0];
    const float* rec_feat  = (const float*)d_in[1];
    const float* lig_coord = (const float*)d_in[2];
    const float* rec_coord = (const float*)d_in[3];
    float* out = (float*)d_out;

    cudaFuncSetAttribute(ff_main_kernel,
                         cudaFuncAttributeMaxDynamicSharedMemorySize,
                         SMEM_BYTES);

    ff_init_kernel<<<1, 32>>>(out);

    // (8, 16, 8) = 1024 CTAs, 1 per SM
    dim3 grid(RDIM / RT, EDIM / ECH, BATCH);
    ff_main_kernel<<<grid, NTHREADS, SMEM_BYTES>>>(lig_feat, rec_feat,
                                                   lig_coord, rec_coord, out);
}